// round 15
// baseline (speedup 1.0000x reference)
#include <cuda_runtime.h>
#include <cuda_bf16.h>
#include <mma.h>
#include <cstdint>
#include <cstring>

using namespace nvcuda;

#define N_USERS 100000
#define N_ITEMS 100000
#define DIM     128
#define NUM_R   4
#define N_EDGES 1000000

#define GRID_U  148
#define TM      64
#define NT      ((N_USERS + TM - 1) / TM)   // 1563

#define SCAN_N  (2 * NUM_R * N_USERS)
#define NTILES  ((SCAN_N + 1023) / 1024)
#define TOT_E   (2 * NUM_R * N_EDGES)

// ---------------- device scratch ----------------
__device__ float g_U[(size_t)N_USERS * DIM];
__device__ float g_I[(size_t)N_ITEMS * DIM];
__device__ float g_AGG[(size_t)N_USERS * DIM];
__device__ __nv_bfloat16 g_Wb[(size_t)5 * 2 * 16384];
__device__ int  g_cnt[SCAN_N];
__device__ int  g_cur[SCAN_N];
__device__ int  g_off[SCAN_N + 1];
__device__ int  g_tile[NTILES];
__device__ int2 g_csr[TOT_E];

// ---------------- count (vectorized: 4 edges per thread) ----------------
__global__ void count_kernel(const int* __restrict__ rows, const int* __restrict__ cols)
{
    int idx = blockIdx.x * blockDim.x + threadIdx.x;       // int4 units
    const int total4 = NUM_R * N_EDGES / 4;
    if (idx >= total4) return;
    int r = (idx * 4) / N_EDGES;                            // uniform: 1M % 4 == 0
    int4 ro = __ldg(&reinterpret_cast<const int4*>(rows)[idx]);
    int4 co = __ldg(&reinterpret_cast<const int4*>(cols)[idx]);
    int* cntU = g_cnt + r * N_USERS;
    int* cntI = g_cnt + NUM_R * N_USERS + r * N_ITEMS;
    atomicAdd(&cntU[ro.x], 1); atomicAdd(&cntU[ro.y], 1);
    atomicAdd(&cntU[ro.z], 1); atomicAdd(&cntU[ro.w], 1);
    atomicAdd(&cntI[co.x], 1); atomicAdd(&cntI[co.y], 1);
    atomicAdd(&cntI[co.z], 1); atomicAdd(&cntI[co.w], 1);
}

// ---------------- scans (scan1 also re-zeroes cnt/cur for the next replay) ------
__global__ __launch_bounds__(256) void scan1_kernel()
{
    __shared__ int ssum[256];
    int t = threadIdx.x;
    int base = blockIdx.x * 1024 + t * 4;
    int c[4];
#pragma unroll
    for (int j = 0; j < 4; ++j) c[j] = (base + j < SCAN_N) ? g_cnt[base + j] : 0;
    // re-zero for next launch / fill cursor
#pragma unroll
    for (int j = 0; j < 4; ++j)
        if (base + j < SCAN_N) { g_cnt[base + j] = 0; g_cur[base + j] = 0; }
    int tsum = c[0] + c[1] + c[2] + c[3];
    ssum[t] = tsum;
    __syncthreads();
#pragma unroll
    for (int o = 1; o < 256; o <<= 1) {
        int v = (t >= o) ? ssum[t - o] : 0;
        __syncthreads();
        ssum[t] += v;
        __syncthreads();
    }
    int run = ssum[t] - tsum;
#pragma unroll
    for (int j = 0; j < 4; ++j) {
        if (base + j < SCAN_N) g_off[base + j] = run;
        run += c[j];
    }
    if (t == 255) g_tile[blockIdx.x] = ssum[255];
}

__global__ __launch_bounds__(1024) void scan2_kernel()
{
    __shared__ int s[1024];
    int t = threadIdx.x;
    int orig = (t < NTILES) ? g_tile[t] : 0;
    s[t] = orig;
    __syncthreads();
#pragma unroll
    for (int o = 1; o < 1024; o <<= 1) {
        int v = (t >= o) ? s[t - o] : 0;
        __syncthreads();
        s[t] += v;
        __syncthreads();
    }
    if (t < NTILES) g_tile[t] = s[t] - orig;
}

__global__ __launch_bounds__(256) void scan3_kernel()
{
    int add = g_tile[blockIdx.x];
    int base = blockIdx.x * 1024 + threadIdx.x * 4;
#pragma unroll
    for (int j = 0; j < 4; ++j)
        if (base + j < SCAN_N) g_off[base + j] += add;
    if (blockIdx.x == 0 && threadIdx.x == 0) g_off[SCAN_N] = TOT_E;
}

// ---------------- CSR fill (vectorized: 4 edges per thread) ----------------
__global__ void fill_kernel(const int* __restrict__ rows, const int* __restrict__ cols,
                            const float* __restrict__ vals)
{
    int idx = blockIdx.x * blockDim.x + threadIdx.x;
    const int total4 = NUM_R * N_EDGES / 4;
    if (idx >= total4) return;
    int r = (idx * 4) / N_EDGES;
    int4   ro = __ldg(&reinterpret_cast<const int4*>(rows)[idx]);
    int4   co = __ldg(&reinterpret_cast<const int4*>(cols)[idx]);
    float4 va = __ldg(&reinterpret_cast<const float4*>(vals)[idx]);
    int rows4[4] = {ro.x, ro.y, ro.z, ro.w};
    int cols4[4] = {co.x, co.y, co.z, co.w};
    float vals4[4] = {va.x, va.y, va.z, va.w};
    const int baseU = r * N_USERS;
    const int baseI = NUM_R * N_USERS + r * N_ITEMS;
#pragma unroll
    for (int j = 0; j < 4; ++j) {
        int vb = __float_as_int(vals4[j]);
        int kR = baseU + rows4[j];
        int pR = g_off[kR] + atomicAdd(&g_cur[kR], 1);
        g_csr[pR] = make_int2(cols4[j], vb);
        int kC = baseI + cols4[j];
        int pC = g_off[kC] + atomicAdd(&g_cur[kC], 1);
        g_csr[pC] = make_int2(rows4[j], vb);
    }
}

// ---------------- CSR SpMM: warp per dst row; writes AGG pre-scaled; 4-edge unroll -
__global__ __launch_bounds__(256) void spmm_csr_kernel(const float* __restrict__ feats,
                                                       int kbase)
{
    int gw = (blockIdx.x * blockDim.x + threadIdx.x) >> 5;
    int lane = threadIdx.x & 31;
    if (gw >= N_USERS) return;
    int e0 = g_off[kbase + gw];
    int e1 = g_off[kbase + gw + 1];
    float4 a0 = make_float4(0.f, 0.f, 0.f, 0.f);
    float4 a1 = make_float4(0.f, 0.f, 0.f, 0.f);
    float4 a2 = make_float4(0.f, 0.f, 0.f, 0.f);
    float4 a3 = make_float4(0.f, 0.f, 0.f, 0.f);
    int e = e0;
    for (; e + 3 < e1; e += 4) {
        int2 p0 = __ldg(&g_csr[e]);
        int2 p1 = __ldg(&g_csr[e + 1]);
        int2 p2 = __ldg(&g_csr[e + 2]);
        int2 p3 = __ldg(&g_csr[e + 3]);
        float4 x0 = __ldg(&reinterpret_cast<const float4*>(feats + (size_t)p0.x * DIM)[lane]);
        float4 x1 = __ldg(&reinterpret_cast<const float4*>(feats + (size_t)p1.x * DIM)[lane]);
        float4 x2 = __ldg(&reinterpret_cast<const float4*>(feats + (size_t)p2.x * DIM)[lane]);
        float4 x3 = __ldg(&reinterpret_cast<const float4*>(feats + (size_t)p3.x * DIM)[lane]);
        float v0 = __int_as_float(p0.y), v1 = __int_as_float(p1.y);
        float v2 = __int_as_float(p2.y), v3 = __int_as_float(p3.y);
        a0.x = fmaf(v0, x0.x, a0.x); a0.y = fmaf(v0, x0.y, a0.y);
        a0.z = fmaf(v0, x0.z, a0.z); a0.w = fmaf(v0, x0.w, a0.w);
        a1.x = fmaf(v1, x1.x, a1.x); a1.y = fmaf(v1, x1.y, a1.y);
        a1.z = fmaf(v1, x1.z, a1.z); a1.w = fmaf(v1, x1.w, a1.w);
        a2.x = fmaf(v2, x2.x, a2.x); a2.y = fmaf(v2, x2.y, a2.y);
        a2.z = fmaf(v2, x2.z, a2.z); a2.w = fmaf(v2, x2.w, a2.w);
        a3.x = fmaf(v3, x3.x, a3.x); a3.y = fmaf(v3, x3.y, a3.y);
        a3.z = fmaf(v3, x3.z, a3.z); a3.w = fmaf(v3, x3.w, a3.w);
    }
    for (; e < e1; ++e) {
        int2 p = __ldg(&g_csr[e]);
        float v = __int_as_float(p.y);
        float4 x = __ldg(&reinterpret_cast<const float4*>(feats + (size_t)p.x * DIM)[lane]);
        a0.x = fmaf(v, x.x, a0.x); a0.y = fmaf(v, x.y, a0.y);
        a0.z = fmaf(v, x.z, a0.z); a0.w = fmaf(v, x.w, a0.w);
    }
    float s = 1.0f / ((float)(e1 - e0) + 1.0f);   // vals are ones => deg == extent
    a0.x = (a0.x + a1.x + a2.x + a3.x) * s;
    a0.y = (a0.y + a1.y + a2.y + a3.y) * s;
    a0.z = (a0.z + a1.z + a2.z + a3.z) * s;
    a0.w = (a0.w + a1.w + a2.w + a3.w) * s;
    reinterpret_cast<float4*>(g_AGG + (size_t)gw * DIM)[lane] = a0;
}

// ---------------- weight prep ----------------
__global__ __launch_bounds__(256) void wprep_kernel(const float* __restrict__ Wp,
                                                    const float* __restrict__ Ws)
{
    int w = blockIdx.x;
    const float* W = (w == 0) ? Wp : Ws + (size_t)(w - 1) * DIM * DIM;
    __nv_bfloat16* hi = g_Wb + (size_t)w * 2 * 16384;
    __nv_bfloat16* lo = hi + 16384;
    for (int e = threadIdx.x; e < DIM * DIM; e += blockDim.x) {
        int k = e >> 7, n = e & 127;
        float x = W[e];
        __nv_bfloat16 h = __float2bfloat16(x);
        __nv_bfloat16 l = __float2bfloat16(x - __bfloat162float(h));
        hi[n * DIM + k] = h;
        lo[n * DIM + k] = l;
    }
}

// ================= persistent WMMA update GEMM =================
#define LDA       136
#define ASTRIDE_B (LDA * 2)
#define SM_STAGE  0
#define SM_AH     (SM_STAGE + 32768)
#define SM_AL     (SM_AH + TM * ASTRIDE_B)
#define SM_B      (SM_AL + TM * ASTRIDE_B)
#define BMAT      (128 * ASTRIDE_B)
#define SM_BYTES  (SM_B + 4 * BMAT)

typedef wmma::fragment<wmma::matrix_a, 16, 16, 16, __nv_bfloat16, wmma::row_major> FragA;
typedef wmma::fragment<wmma::matrix_b, 16, 16, 16, __nv_bfloat16, wmma::col_major> FragB;
typedef wmma::fragment<wmma::accumulator, 16, 16, 16, float> FragC;

__device__ __forceinline__ uint32_t smem_u32(const void* p) {
    uint32_t a;
    asm("{ .reg .u64 t; cvta.to.shared.u64 t, %1; cvt.u32.u64 %0, t; }" : "=r"(a) : "l"(p));
    return a;
}
__device__ __forceinline__ void cp_async16(uint32_t smem_dst, const void* gsrc) {
    asm volatile("cp.async.cg.shared.global [%0], [%1], 16;" :: "r"(smem_dst), "l"(gsrc));
}
#define CP_COMMIT() asm volatile("cp.async.commit_group;" ::: "memory")
#define CP_WAIT0()  asm volatile("cp.async.wait_group 0;" ::: "memory")

__device__ __forceinline__ void stage_load(const float* __restrict__ src, int bm, int M,
                                           uint32_t stageAddr, int tid)
{
#pragma unroll
    for (int i = 0; i < 8; ++i) {
        int idx = i * 256 + tid;
        int r = idx >> 5, c4 = idx & 31;
        int rowg = bm + r;
        if (rowg >= M) rowg = M - 1;
        cp_async16(stageAddr + (uint32_t)idx * 16, src + (size_t)rowg * DIM + c4 * 4);
    }
    CP_COMMIT();
}

__device__ __forceinline__ void cvt_stage(const char* __restrict__ stage, char* hi, char* lo,
                                          int tid)
{
#pragma unroll
    for (int it = 0; it < 8; ++it) {
        int idx = it * 256 + tid;
        int r = idx >> 5, c4 = idx & 31;
        float4 v = *reinterpret_cast<const float4*>(stage + (size_t)idx * 16);
        __nv_bfloat162 h01 = __floats2bfloat162_rn(v.x, v.y);
        __nv_bfloat162 h23 = __floats2bfloat162_rn(v.z, v.w);
        __nv_bfloat162 l01 = __floats2bfloat162_rn(v.x - __bfloat162float(h01.x),
                                                   v.y - __bfloat162float(h01.y));
        __nv_bfloat162 l23 = __floats2bfloat162_rn(v.z - __bfloat162float(h23.x),
                                                   v.w - __bfloat162float(h23.y));
        uint32_t off = (uint32_t)r * ASTRIDE_B + (uint32_t)c4 * 8;
        uint2 hv, lv;
        memcpy(&hv.x, &h01, 4); memcpy(&hv.y, &h23, 4);
        memcpy(&lv.x, &l01, 4); memcpy(&lv.y, &l23, 4);
        *reinterpret_cast<uint2*>(hi + off) = hv;
        *reinterpret_cast<uint2*>(lo + off) = lv;
    }
}

// fused 3-term split phase, warp tile m32 x n32
__device__ __forceinline__ void mma_phase(const __nv_bfloat16* aHs, const __nv_bfloat16* aLs,
                                          const __nv_bfloat16* bHs, const __nv_bfloat16* bLs,
                                          FragC (&acc)[2][2])
{
#pragma unroll
    for (int ks = 0; ks < 8; ++ks) {
        FragA ah[2], al[2];
        FragB bh[2], bl[2];
#pragma unroll
        for (int mi = 0; mi < 2; ++mi) {
            wmma::load_matrix_sync(ah[mi], aHs + (size_t)(mi * 16) * LDA + ks * 16, LDA);
            wmma::load_matrix_sync(al[mi], aLs + (size_t)(mi * 16) * LDA + ks * 16, LDA);
        }
#pragma unroll
        for (int j = 0; j < 2; ++j) {
            wmma::load_matrix_sync(bh[j], bHs + (size_t)(j * 16) * LDA + ks * 16, LDA);
            wmma::load_matrix_sync(bl[j], bLs + (size_t)(j * 16) * LDA + ks * 16, LDA);
        }
#pragma unroll
        for (int mi = 0; mi < 2; ++mi)
#pragma unroll
            for (int j = 0; j < 2; ++j) {
                wmma::mma_sync(acc[mi][j], ah[mi], bh[j], acc[mi][j]);
                wmma::mma_sync(acc[mi][j], ah[mi], bl[j], acc[mi][j]);
                wmma::mma_sync(acc[mi][j], al[mi], bh[j], acc[mi][j]);
            }
    }
}

// Xin: pre-update embeddings; Xout: updated embeddings (nullable if dead);
// outp: if non-null, also writes leaky_relu(result) there (final round fusion).
__global__ __launch_bounds__(256, 1)
void update_mma_kernel(const float* __restrict__ Xin, float* __restrict__ Xout,
                       const __nv_bfloat16* __restrict__ wp_pair,
                       const __nv_bfloat16* __restrict__ ws_pair, int M,
                       float* __restrict__ outp)
{
    extern __shared__ char sm[];
    const uint32_t sb = smem_u32(sm);
    const int tid = threadIdx.x;
    const int wid = tid >> 5;
    const int mg  = wid & 1;
    const int ng  = wid >> 1;

    {
        const float4* srcs[4] = {
            reinterpret_cast<const float4*>(wp_pair),
            reinterpret_cast<const float4*>(wp_pair + 16384),
            reinterpret_cast<const float4*>(ws_pair),
            reinterpret_cast<const float4*>(ws_pair + 16384)};
#pragma unroll
        for (int w = 0; w < 4; ++w) {
            char* dst = sm + SM_B + w * BMAT;
#pragma unroll
            for (int i = 0; i < 8; ++i) {
                int idx = i * 256 + tid;
                int row = idx >> 4, c = idx & 15;
                *reinterpret_cast<float4*>(dst + (uint32_t)row * ASTRIDE_B + c * 16) = srcs[w][idx];
            }
        }
    }

    const uint32_t stageAddr = sb + SM_STAGE;
    char* stage = sm + SM_STAGE;
    char* aHbuf = sm + SM_AH;
    char* aLbuf = sm + SM_AL;

    const __nv_bfloat16* aH = (const __nv_bfloat16*)aHbuf + (size_t)mg * 32 * LDA;
    const __nv_bfloat16* aL = (const __nv_bfloat16*)aLbuf + (size_t)mg * 32 * LDA;
    const __nv_bfloat16* bPH = (const __nv_bfloat16*)(sm + SM_B + 0 * BMAT) + (size_t)ng * 32 * LDA;
    const __nv_bfloat16* bPL = (const __nv_bfloat16*)(sm + SM_B + 1 * BMAT) + (size_t)ng * 32 * LDA;
    const __nv_bfloat16* bSH = (const __nv_bfloat16*)(sm + SM_B + 2 * BMAT) + (size_t)ng * 32 * LDA;
    const __nv_bfloat16* bSL = (const __nv_bfloat16*)(sm + SM_B + 3 * BMAT) + (size_t)ng * 32 * LDA;

    stage_load(Xin, (int)blockIdx.x * TM, M, stageAddr, tid);

    for (int t = blockIdx.x; t < NT; t += GRID_U) {
        const int bm = t * TM;

        FragC acc[2][2];
#pragma unroll
        for (int mi = 0; mi < 2; ++mi)
#pragma unroll
            for (int j = 0; j < 2; ++j) wmma::fill_fragment(acc[mi][j], 0.0f);

        // phase 0: A = X, B = Wp
        CP_WAIT0();
        __syncthreads();
        cvt_stage(stage, aHbuf, aLbuf, tid);
        __syncthreads();
        stage_load(g_AGG, bm, M, stageAddr, tid);
        mma_phase(aH, aL, bPH, bPL, acc);

        // phase 1: A = scaled AGG, B = Ws
        CP_WAIT0();
        __syncthreads();
        cvt_stage(stage, aHbuf, aLbuf, tid);
        __syncthreads();
        if (t + GRID_U < NT)
            stage_load(Xin, (t + GRID_U) * TM, M, stageAddr, tid);
        mma_phase(aH, aL, bSH, bSL, acc);

        // epilogue
#pragma unroll
        for (int mi = 0; mi < 2; ++mi) {
            int row0 = bm + mg * 32 + mi * 16;
            if (row0 < M) {
#pragma unroll
                for (int j = 0; j < 2; ++j) {
                    if (Xout)
                        wmma::store_matrix_sync(Xout + (size_t)row0 * DIM + ng * 32 + j * 16,
                                                acc[mi][j], DIM, wmma::mem_row_major);
                    if (outp) {
                        FragC lf;
#pragma unroll
                        for (int e2 = 0; e2 < lf.num_elements; ++e2) {
                            float x = acc[mi][j].x[e2];
                            lf.x[e2] = x > 0.f ? x : 0.01f * x;
                        }
                        wmma::store_matrix_sync(outp + (size_t)row0 * DIM + ng * 32 + j * 16,
                                                lf, DIM, wmma::mem_row_major);
                    }
                }
            }
        }
    }
}

// ---------------- launch ----------------
extern "C" void kernel_launch(void* const* d_in, const int* in_sizes, int n_in,
                              void* d_out, int out_size)
{
    const float* u_emb = (const float*)d_in[0];
    const float* i_emb = (const float*)d_in[1];
    const float* Wp    = (const float*)d_in[2];
    const float* Ws    = (const float*)d_in[3];
    const float* vals  = (const float*)d_in[4];
    const int*   rows  = (const int*)d_in[5];
    const int*   cols  = (const int*)d_in[6];
    float*       out   = (float*)d_out;

    void *pU, *pI, *pWb;
    cudaGetSymbolAddress(&pU,  g_U);
    cudaGetSymbolAddress(&pI,  g_I);
    cudaGetSymbolAddress(&pWb, g_Wb);

    cudaFuncSetAttribute(update_mma_kernel, cudaFuncAttributeMaxDynamicSharedMemorySize, SM_BYTES);

    wprep_kernel<<<5, 256>>>(Wp, Ws);
    const int edges4 = NUM_R * N_EDGES / 4;
    count_kernel<<<(edges4 + 255) / 256, 256>>>(rows, cols);
    scan1_kernel<<<NTILES, 256>>>();
    scan2_kernel<<<1, 1024>>>();
    scan3_kernel<<<NTILES, 256>>>();
    fill_kernel<<<(edges4 + 255) / 256, 256>>>(rows, cols, vals);

    const int spmm_blocks = (N_USERS * 32 + 255) / 256;
    const __nv_bfloat16* wb = (const __nv_bfloat16*)pWb;

    for (int r = 0; r < NUM_R; ++r) {
        const __nv_bfloat16* wp_pair = wb;
        const __nv_bfloat16* ws_pair = wb + (size_t)(1 + r) * 2 * 16384;
        const bool first = (r == 0);
        const bool last  = (r == NUM_R - 1);

        // ---- u update ----
        spmm_csr_kernel<<<spmm_blocks, 256>>>(first ? i_emb : (const float*)pI, r * N_USERS);
        update_mma_kernel<<<GRID_U, 256, SM_BYTES>>>(
            first ? u_emb : (const float*)pU, (float*)pU, wp_pair, ws_pair, N_USERS,
            last ? out : nullptr);

        // ---- i update (uses updated U); final Xout is dead -> skip it ----
        spmm_csr_kernel<<<spmm_blocks, 256>>>((const float*)pU, (NUM_R + r) * N_ITEMS);
        update_mma_kernel<<<GRID_U, 256, SM_BYTES>>>(
            first ? i_emb : (const float*)pI, last ? nullptr : (float*)pI,
            wp_pair, ws_pair, N_ITEMS,
            last ? out + (size_t)N_USERS * DIM : nullptr);
    }
}

// round 16
// speedup vs baseline: 1.0595x; 1.0595x over previous
#include <cuda_runtime.h>
#include <cuda_bf16.h>
#include <mma.h>
#include <cstdint>
#include <cstring>

using namespace nvcuda;

#define N_USERS 100000
#define N_ITEMS 100000
#define DIM     128
#define NUM_R   4
#define N_EDGES 1000000

#define GRID_U  148
#define TM      64
#define NT      ((N_USERS + TM - 1) / TM)   // 1563

#define SCAN_N  (2 * NUM_R * N_USERS)
#define NTILES  ((SCAN_N + 1023) / 1024)
#define TOT_E   (2 * NUM_R * N_EDGES)

// ---------------- device scratch ----------------
__device__ float g_U[(size_t)N_USERS * DIM];
__device__ float g_I[(size_t)N_ITEMS * DIM];
__device__ float g_AGG[(size_t)N_USERS * DIM];
__device__ __nv_bfloat16 g_Wb[(size_t)5 * 2 * 16384];
__device__ int  g_cnt[SCAN_N];
__device__ int  g_cur[SCAN_N];
__device__ int  g_off[SCAN_N + 1];
__device__ int  g_tile[NTILES];
__device__ int2 g_csr[TOT_E];

// ---------------- count (deg == count since vals are ones) ----------------
__global__ void count_kernel(const int* __restrict__ rows, const int* __restrict__ cols)
{
    int idx = blockIdx.x * blockDim.x + threadIdx.x;
    if (idx >= NUM_R * N_EDGES) return;
    int r = idx / N_EDGES;
    atomicAdd(&g_cnt[r * N_USERS + rows[idx]], 1);
    atomicAdd(&g_cnt[NUM_R * N_USERS + r * N_ITEMS + cols[idx]], 1);
}

// ---------------- scans (scan1 also re-zeroes cnt/cur for the next replay) ------
__global__ __launch_bounds__(256) void scan1_kernel()
{
    __shared__ int ssum[256];
    int t = threadIdx.x;
    int base = blockIdx.x * 1024 + t * 4;
    int c[4];
#pragma unroll
    for (int j = 0; j < 4; ++j) c[j] = (base + j < SCAN_N) ? g_cnt[base + j] : 0;
#pragma unroll
    for (int j = 0; j < 4; ++j)
        if (base + j < SCAN_N) { g_cnt[base + j] = 0; g_cur[base + j] = 0; }
    int tsum = c[0] + c[1] + c[2] + c[3];
    ssum[t] = tsum;
    __syncthreads();
#pragma unroll
    for (int o = 1; o < 256; o <<= 1) {
        int v = (t >= o) ? ssum[t - o] : 0;
        __syncthreads();
        ssum[t] += v;
        __syncthreads();
    }
    int run = ssum[t] - tsum;
#pragma unroll
    for (int j = 0; j < 4; ++j) {
        if (base + j < SCAN_N) g_off[base + j] = run;
        run += c[j];
    }
    if (t == 255) g_tile[blockIdx.x] = ssum[255];
}

__global__ __launch_bounds__(1024) void scan2_kernel()
{
    __shared__ int s[1024];
    int t = threadIdx.x;
    int orig = (t < NTILES) ? g_tile[t] : 0;
    s[t] = orig;
    __syncthreads();
#pragma unroll
    for (int o = 1; o < 1024; o <<= 1) {
        int v = (t >= o) ? s[t - o] : 0;
        __syncthreads();
        s[t] += v;
        __syncthreads();
    }
    if (t < NTILES) g_tile[t] = s[t] - orig;
}

__global__ __launch_bounds__(256) void scan3_kernel()
{
    int add = g_tile[blockIdx.x];
    int base = blockIdx.x * 1024 + threadIdx.x * 4;
#pragma unroll
    for (int j = 0; j < 4; ++j)
        if (base + j < SCAN_N) g_off[base + j] += add;
    if (blockIdx.x == 0 && threadIdx.x == 0) g_off[SCAN_N] = TOT_E;
}

// ---------------- CSR fill ----------------
__global__ void fill_kernel(const int* __restrict__ rows, const int* __restrict__ cols,
                            const float* __restrict__ vals)
{
    int idx = blockIdx.x * blockDim.x + threadIdx.x;
    if (idx >= NUM_R * N_EDGES) return;
    int r = idx / N_EDGES;
    int row = rows[idx], col = cols[idx];
    int vb = __float_as_int(vals[idx]);
    int kR = r * N_USERS + row;
    int pR = g_off[kR] + atomicAdd(&g_cur[kR], 1);
    g_csr[pR] = make_int2(col, vb);
    int kC = NUM_R * N_USERS + r * N_ITEMS + col;
    int pC = g_off[kC] + atomicAdd(&g_cur[kC], 1);
    g_csr[pC] = make_int2(row, vb);
}

// ---------------- CSR SpMM: warp per dst row; writes AGG pre-scaled by 1/(deg+1) ----
__global__ __launch_bounds__(256) void spmm_csr_kernel(const float* __restrict__ feats,
                                                       int kbase)
{
    int gw = (blockIdx.x * blockDim.x + threadIdx.x) >> 5;
    int lane = threadIdx.x & 31;
    if (gw >= N_USERS) return;
    int e0 = g_off[kbase + gw];
    int e1 = g_off[kbase + gw + 1];
    float4 acc0 = make_float4(0.f, 0.f, 0.f, 0.f);
    float4 acc1 = make_float4(0.f, 0.f, 0.f, 0.f);
    int e = e0;
    for (; e + 1 < e1; e += 2) {
        int2 p0 = __ldg(&g_csr[e]);
        int2 p1 = __ldg(&g_csr[e + 1]);
        float v0 = __int_as_float(p0.y), v1 = __int_as_float(p1.y);
        float4 x0 = __ldg(&reinterpret_cast<const float4*>(feats + (size_t)p0.x * DIM)[lane]);
        float4 x1 = __ldg(&reinterpret_cast<const float4*>(feats + (size_t)p1.x * DIM)[lane]);
        acc0.x = fmaf(v0, x0.x, acc0.x); acc0.y = fmaf(v0, x0.y, acc0.y);
        acc0.z = fmaf(v0, x0.z, acc0.z); acc0.w = fmaf(v0, x0.w, acc0.w);
        acc1.x = fmaf(v1, x1.x, acc1.x); acc1.y = fmaf(v1, x1.y, acc1.y);
        acc1.z = fmaf(v1, x1.z, acc1.z); acc1.w = fmaf(v1, x1.w, acc1.w);
    }
    if (e < e1) {
        int2 p = __ldg(&g_csr[e]);
        float v = __int_as_float(p.y);
        float4 x = __ldg(&reinterpret_cast<const float4*>(feats + (size_t)p.x * DIM)[lane]);
        acc0.x = fmaf(v, x.x, acc0.x); acc0.y = fmaf(v, x.y, acc0.y);
        acc0.z = fmaf(v, x.z, acc0.z); acc0.w = fmaf(v, x.w, acc0.w);
    }
    float s = 1.0f / ((float)(e1 - e0) + 1.0f);   // vals are ones => deg == extent
    acc0.x = (acc0.x + acc1.x) * s; acc0.y = (acc0.y + acc1.y) * s;
    acc0.z = (acc0.z + acc1.z) * s; acc0.w = (acc0.w + acc1.w) * s;
    reinterpret_cast<float4*>(g_AGG + (size_t)gw * DIM)[lane] = acc0;
}

// ---------------- weight prep ----------------
__global__ __launch_bounds__(256) void wprep_kernel(const float* __restrict__ Wp,
                                                    const float* __restrict__ Ws)
{
    int w = blockIdx.x;
    const float* W = (w == 0) ? Wp : Ws + (size_t)(w - 1) * DIM * DIM;
    __nv_bfloat16* hi = g_Wb + (size_t)w * 2 * 16384;
    __nv_bfloat16* lo = hi + 16384;
    for (int e = threadIdx.x; e < DIM * DIM; e += blockDim.x) {
        int k = e >> 7, n = e & 127;
        float x = W[e];
        __nv_bfloat16 h = __float2bfloat16(x);
        __nv_bfloat16 l = __float2bfloat16(x - __bfloat162float(h));
        hi[n * DIM + k] = h;
        lo[n * DIM + k] = l;
    }
}

// ================= persistent WMMA update GEMM =================
#define LDA       136
#define ASTRIDE_B (LDA * 2)
#define SM_STAGE  0
#define SM_AH     (SM_STAGE + 32768)
#define SM_AL     (SM_AH + TM * ASTRIDE_B)
#define SM_B      (SM_AL + TM * ASTRIDE_B)
#define BMAT      (128 * ASTRIDE_B)
#define SM_BYTES  (SM_B + 4 * BMAT)

typedef wmma::fragment<wmma::matrix_a, 16, 16, 16, __nv_bfloat16, wmma::row_major> FragA;
typedef wmma::fragment<wmma::matrix_b, 16, 16, 16, __nv_bfloat16, wmma::col_major> FragB;
typedef wmma::fragment<wmma::accumulator, 16, 16, 16, float> FragC;

__device__ __forceinline__ uint32_t smem_u32(const void* p) {
    uint32_t a;
    asm("{ .reg .u64 t; cvta.to.shared.u64 t, %1; cvt.u32.u64 %0, t; }" : "=r"(a) : "l"(p));
    return a;
}
__device__ __forceinline__ void cp_async16(uint32_t smem_dst, const void* gsrc) {
    asm volatile("cp.async.cg.shared.global [%0], [%1], 16;" :: "r"(smem_dst), "l"(gsrc));
}
#define CP_COMMIT() asm volatile("cp.async.commit_group;" ::: "memory")
#define CP_WAIT0()  asm volatile("cp.async.wait_group 0;" ::: "memory")

__device__ __forceinline__ void stage_load(const float* __restrict__ src, int bm, int M,
                                           uint32_t stageAddr, int tid)
{
#pragma unroll
    for (int i = 0; i < 8; ++i) {
        int idx = i * 256 + tid;
        int r = idx >> 5, c4 = idx & 31;
        int rowg = bm + r;
        if (rowg >= M) rowg = M - 1;
        cp_async16(stageAddr + (uint32_t)idx * 16, src + (size_t)rowg * DIM + c4 * 4);
    }
    CP_COMMIT();
}

__device__ __forceinline__ void cvt_stage(const char* __restrict__ stage, char* hi, char* lo,
                                          int tid)
{
#pragma unroll
    for (int it = 0; it < 8; ++it) {
        int idx = it * 256 + tid;
        int r = idx >> 5, c4 = idx & 31;
        float4 v = *reinterpret_cast<const float4*>(stage + (size_t)idx * 16);
        __nv_bfloat162 h01 = __floats2bfloat162_rn(v.x, v.y);
        __nv_bfloat162 h23 = __floats2bfloat162_rn(v.z, v.w);
        __nv_bfloat162 l01 = __floats2bfloat162_rn(v.x - __bfloat162float(h01.x),
                                                   v.y - __bfloat162float(h01.y));
        __nv_bfloat162 l23 = __floats2bfloat162_rn(v.z - __bfloat162float(h23.x),
                                                   v.w - __bfloat162float(h23.y));
        uint32_t off = (uint32_t)r * ASTRIDE_B + (uint32_t)c4 * 8;
        uint2 hv, lv;
        memcpy(&hv.x, &h01, 4); memcpy(&hv.y, &h23, 4);
        memcpy(&lv.x, &l01, 4); memcpy(&lv.y, &l23, 4);
        *reinterpret_cast<uint2*>(hi + off) = hv;
        *reinterpret_cast<uint2*>(lo + off) = lv;
    }
}

// fused 3-term split phase, warp tile m32 x n32
__device__ __forceinline__ void mma_phase(const __nv_bfloat16* aHs, const __nv_bfloat16* aLs,
                                          const __nv_bfloat16* bHs, const __nv_bfloat16* bLs,
                                          FragC (&acc)[2][2])
{
#pragma unroll
    for (int ks = 0; ks < 8; ++ks) {
        FragA ah[2], al[2];
        FragB bh[2], bl[2];
#pragma unroll
        for (int mi = 0; mi < 2; ++mi) {
            wmma::load_matrix_sync(ah[mi], aHs + (size_t)(mi * 16) * LDA + ks * 16, LDA);
            wmma::load_matrix_sync(al[mi], aLs + (size_t)(mi * 16) * LDA + ks * 16, LDA);
        }
#pragma unroll
        for (int j = 0; j < 2; ++j) {
            wmma::load_matrix_sync(bh[j], bHs + (size_t)(j * 16) * LDA + ks * 16, LDA);
            wmma::load_matrix_sync(bl[j], bLs + (size_t)(j * 16) * LDA + ks * 16, LDA);
        }
#pragma unroll
        for (int mi = 0; mi < 2; ++mi)
#pragma unroll
            for (int j = 0; j < 2; ++j) {
                wmma::mma_sync(acc[mi][j], ah[mi], bh[j], acc[mi][j]);
                wmma::mma_sync(acc[mi][j], ah[mi], bl[j], acc[mi][j]);
                wmma::mma_sync(acc[mi][j], al[mi], bh[j], acc[mi][j]);
            }
    }
}

// Xin: pre-update embeddings; Xout: updated embeddings (nullable if dead);
// outp: if non-null, also writes leaky_relu(result) there (final round fusion).
__global__ __launch_bounds__(256, 1)
void update_mma_kernel(const float* __restrict__ Xin, float* __restrict__ Xout,
                       const __nv_bfloat16* __restrict__ wp_pair,
                       const __nv_bfloat16* __restrict__ ws_pair, int M,
                       float* __restrict__ outp)
{
    extern __shared__ char sm[];
    const uint32_t sb = smem_u32(sm);
    const int tid = threadIdx.x;
    const int wid = tid >> 5;
    const int mg  = wid & 1;
    const int ng  = wid >> 1;

    {
        const float4* srcs[4] = {
            reinterpret_cast<const float4*>(wp_pair),
            reinterpret_cast<const float4*>(wp_pair + 16384),
            reinterpret_cast<const float4*>(ws_pair),
            reinterpret_cast<const float4*>(ws_pair + 16384)};
#pragma unroll
        for (int w = 0; w < 4; ++w) {
            char* dst = sm + SM_B + w * BMAT;
#pragma unroll
            for (int i = 0; i < 8; ++i) {
                int idx = i * 256 + tid;
                int row = idx >> 4, c = idx & 15;
                *reinterpret_cast<float4*>(dst + (uint32_t)row * ASTRIDE_B + c * 16) = srcs[w][idx];
            }
        }
    }

    const uint32_t stageAddr = sb + SM_STAGE;
    char* stage = sm + SM_STAGE;
    char* aHbuf = sm + SM_AH;
    char* aLbuf = sm + SM_AL;

    const __nv_bfloat16* aH = (const __nv_bfloat16*)aHbuf + (size_t)mg * 32 * LDA;
    const __nv_bfloat16* aL = (const __nv_bfloat16*)aLbuf + (size_t)mg * 32 * LDA;
    const __nv_bfloat16* bPH = (const __nv_bfloat16*)(sm + SM_B + 0 * BMAT) + (size_t)ng * 32 * LDA;
    const __nv_bfloat16* bPL = (const __nv_bfloat16*)(sm + SM_B + 1 * BMAT) + (size_t)ng * 32 * LDA;
    const __nv_bfloat16* bSH = (const __nv_bfloat16*)(sm + SM_B + 2 * BMAT) + (size_t)ng * 32 * LDA;
    const __nv_bfloat16* bSL = (const __nv_bfloat16*)(sm + SM_B + 3 * BMAT) + (size_t)ng * 32 * LDA;

    stage_load(Xin, (int)blockIdx.x * TM, M, stageAddr, tid);

    for (int t = blockIdx.x; t < NT; t += GRID_U) {
        const int bm = t * TM;

        FragC acc[2][2];
#pragma unroll
        for (int mi = 0; mi < 2; ++mi)
#pragma unroll
            for (int j = 0; j < 2; ++j) wmma::fill_fragment(acc[mi][j], 0.0f);

        // phase 0: A = X, B = Wp
        CP_WAIT0();
        __syncthreads();
        cvt_stage(stage, aHbuf, aLbuf, tid);
        __syncthreads();
        stage_load(g_AGG, bm, M, stageAddr, tid);
        mma_phase(aH, aL, bPH, bPL, acc);

        // phase 1: A = scaled AGG, B = Ws
        CP_WAIT0();
        __syncthreads();
        cvt_stage(stage, aHbuf, aLbuf, tid);
        __syncthreads();
        if (t + GRID_U < NT)
            stage_load(Xin, (t + GRID_U) * TM, M, stageAddr, tid);
        mma_phase(aH, aL, bSH, bSL, acc);

        // epilogue
#pragma unroll
        for (int mi = 0; mi < 2; ++mi) {
            int row0 = bm + mg * 32 + mi * 16;
            if (row0 < M) {
#pragma unroll
                for (int j = 0; j < 2; ++j) {
                    if (Xout)
                        wmma::store_matrix_sync(Xout + (size_t)row0 * DIM + ng * 32 + j * 16,
                                                acc[mi][j], DIM, wmma::mem_row_major);
                    if (outp) {
                        FragC lf;
#pragma unroll
                        for (int e2 = 0; e2 < lf.num_elements; ++e2) {
                            float x = acc[mi][j].x[e2];
                            lf.x[e2] = x > 0.f ? x : 0.01f * x;
                        }
                        wmma::store_matrix_sync(outp + (size_t)row0 * DIM + ng * 32 + j * 16,
                                                lf, DIM, wmma::mem_row_major);
                    }
                }
            }
        }
    }
}

// ---------------- launch ----------------
extern "C" void kernel_launch(void* const* d_in, const int* in_sizes, int n_in,
                              void* d_out, int out_size)
{
    const float* u_emb = (const float*)d_in[0];
    const float* i_emb = (const float*)d_in[1];
    const float* Wp    = (const float*)d_in[2];
    const float* Ws    = (const float*)d_in[3];
    const float* vals  = (const float*)d_in[4];
    const int*   rows  = (const int*)d_in[5];
    const int*   cols  = (const int*)d_in[6];
    float*       out   = (float*)d_out;

    void *pU, *pI, *pWb;
    cudaGetSymbolAddress(&pU,  g_U);
    cudaGetSymbolAddress(&pI,  g_I);
    cudaGetSymbolAddress(&pWb, g_Wb);

    cudaFuncSetAttribute(update_mma_kernel, cudaFuncAttributeMaxDynamicSharedMemorySize, SM_BYTES);

    wprep_kernel<<<5, 256>>>(Wp, Ws);
    count_kernel<<<(NUM_R * N_EDGES + 255) / 256, 256>>>(rows, cols);
    scan1_kernel<<<NTILES, 256>>>();
    scan2_kernel<<<1, 1024>>>();
    scan3_kernel<<<NTILES, 256>>>();
    fill_kernel<<<(NUM_R * N_EDGES + 255) / 256, 256>>>(rows, cols, vals);

    const int spmm_blocks = (N_USERS * 32 + 255) / 256;
    const __nv_bfloat16* wb = (const __nv_bfloat16*)pWb;

    for (int r = 0; r < NUM_R; ++r) {
        const __nv_bfloat16* wp_pair = wb;
        const __nv_bfloat16* ws_pair = wb + (size_t)(1 + r) * 2 * 16384;
        const bool first = (r == 0);
        const bool last  = (r == NUM_R - 1);

        // ---- u update ----
        spmm_csr_kernel<<<spmm_blocks, 256>>>(first ? i_emb : (const float*)pI, r * N_USERS);
        update_mma_kernel<<<GRID_U, 256, SM_BYTES>>>(
            first ? u_emb : (const float*)pU, (float*)pU, wp_pair, ws_pair, N_USERS,
            last ? out : nullptr);

        // ---- i update (uses updated U); final Xout is dead -> skip it ----
        spmm_csr_kernel<<<spmm_blocks, 256>>>((const float*)pU, (NUM_R + r) * N_ITEMS);
        update_mma_kernel<<<GRID_U, 256, SM_BYTES>>>(
            first ? i_emb : (const float*)pI, last ? nullptr : (float*)pI,
            wp_pair, ws_pair, N_ITEMS,
            last ? out + (size_t)N_USERS * DIM : nullptr);
    }
}